// round 5
// baseline (speedup 1.0000x reference)
#include <cuda_runtime.h>

// MaxOccurrencePool: sliding-window (K=9) mode-with-tie-average + max-count over
// integer values 0..4 (values 1..4 counted, bin0 only when window empty).
// x: [B=8, L=131072, C=16] f32. Outputs: out [B,L-1,C] f32 then density [B,L-1,C] f32.
//
// R4: issue-bound fix. consume() (76 instr/step) replaced by 2-level smem LUT:
//   state = nibble-packed 4-bin histogram (16 bits, counts<=9)
//   LUT1[state] -> byte (den | tiecode<<4)    (~39KB smem)
//   LUT2[byte]  -> float2(out, den)           (2KB smem)
// h kept as two packed-pair regs; ring stores packed one-hots (no recompute).

#define BB    8
#define LL    131072
#define LOUT  131071               // L - 1 output positions
#define U     28                   // positions per warp (3*9 + 1)
#define NWARP ((LOUT + U - 1) / U) // 4682
#define WPB   16                   // warps per CTA (512 threads)
#define NBLK  ((NWARP + WPB - 1) / WPB)  // 293 CTAs (one wave at 2 CTA/SM)

#define LUT1_SIZE 39424            // covers max reachable index 0x9999 = 39321
#define SMEM_BYTES (LUT1_SIZE + 256 * 8)

// incoming one-hot nibble for value iv in 0..4: nibble (iv-1) = 1, or 0 for iv==0
__device__ __forceinline__ unsigned onib(unsigned iv) {
    return __funnelshift_lc(0x10000000u, 0u, iv << 2);
}

template <bool FULL>
__device__ __forceinline__ void step(int l, int ji, int lend,
                                     const float4 *__restrict__ xin,
                                     float4 *__restrict__ outp,
                                     float4 *__restrict__ denp,
                                     unsigned &hA, unsigned &hB,
                                     unsigned ringA[9], unsigned ringB[9],
                                     float4 &cur,
                                     const unsigned char *__restrict__ lut1,
                                     const float2 *__restrict__ lut2) {
    unsigned a0 = (unsigned)(int)cur.x, a1 = (unsigned)(int)cur.y;
    unsigned a2 = (unsigned)(int)cur.z, a3 = (unsigned)(int)cur.w;

    // prefetch next incoming element (position l+6)
    float4 nxt = make_float4(0.f, 0.f, 0.f, 0.f);
    int pn = l + 6;
    if (FULL) {
        nxt = xin[pn * 4];
    } else if ((unsigned)pn < (unsigned)LL) {
        nxt = xin[pn * 4];
    }

    unsigned inA = onib(a0) | (onib(a1) << 16);
    unsigned inB = onib(a2) | (onib(a3) << 16);
    hA += inA - ringA[ji]; ringA[ji] = inA;
    hB += inB - ringB[ji]; ringB[ji] = inB;

    unsigned b0 = lut1[hA & 0xFFFFu];
    unsigned b1 = lut1[hA >> 16];
    unsigned b2 = lut1[hB & 0xFFFFu];
    unsigned b3 = lut1[hB >> 16];
    float2 r0 = lut2[b0];
    float2 r1 = lut2[b1];
    float2 r2 = lut2[b2];
    float2 r3 = lut2[b3];

    if (FULL || l < lend) {
        __stcs(&outp[l * 4], make_float4(r0.x, r1.x, r2.x, r3.x));
        __stcs(&denp[l * 4], make_float4(r0.y, r1.y, r2.y, r3.y));
    }
    cur = nxt;
}

template <bool FULL>
__device__ __forceinline__ void run_chunk(const float4 *__restrict__ xin,
                                          float4 *__restrict__ outp,
                                          float4 *__restrict__ denp,
                                          int l0, int lend,
                                          const unsigned char *__restrict__ lut1,
                                          const float2 *__restrict__ lut2) {
    unsigned hA = 0, hB = 0;
    unsigned ringA[9], ringB[9];

    // Prefill with positions p = l0-4 .. l0+4. OOB (padding) -> value 0.
    #pragma unroll
    for (int k = 0; k < 9; k++) {
        int p = l0 - 4 + k;
        float4 v = make_float4(0.f, 0.f, 0.f, 0.f);
        if ((unsigned)p < (unsigned)LL) v = xin[p * 4];
        unsigned iA = onib((unsigned)(int)v.x) | (onib((unsigned)(int)v.y) << 16);
        unsigned iB = onib((unsigned)(int)v.z) | (onib((unsigned)(int)v.w) << 16);
        ringA[k] = iA; ringB[k] = iB;
        hA += iA; hB += iB;
    }

    float4 cur = make_float4(0.f, 0.f, 0.f, 0.f);
    {
        int p = l0 + 5;
        if (FULL || (unsigned)p < (unsigned)LL) cur = xin[p * 4];
    }

    // 27 = 3 full ring periods (slot indices compile-time), then 1 epilogue (slot 0).
    #pragma unroll 1
    for (int jo = 0; jo < 3; jo++) {
        #pragma unroll
        for (int ji = 0; ji < 9; ji++)
            step<FULL>(l0 + jo * 9 + ji, ji, lend, xin, outp, denp,
                       hA, hB, ringA, ringB, cur, lut1, lut2);
    }
    step<FULL>(l0 + 27, 0, lend, xin, outp, denp, hA, hB, ringA, ringB, cur, lut1, lut2);
}

__global__ void __launch_bounds__(512, 2)
MaxOccurrencePool_kernel(const float *__restrict__ x, float *__restrict__ out) {
    extern __shared__ char smem[];
    unsigned char *lut1 = (unsigned char *)smem;
    float2 *lut2 = (float2 *)(smem + LUT1_SIZE);

    // ---- build LUT1: state (nibble counts c1..c4) -> byte (den | tiecode<<4) ----
    // cover the [0,9]^4 superset of reachable states (sum<=9); others never read.
    for (int t = threadIdx.x; t < 10000; t += 512) {
        unsigned c1 = t % 10u;  unsigned r = t / 10u;
        unsigned c2 = r % 10u;  r /= 10u;
        unsigned c3 = r % 10u;  unsigned c4 = r / 10u;
        unsigned state = c1 | (c2 << 4) | (c3 << 8) | (c4 << 12);
        unsigned u = c1 | (c2 << 8) | (c3 << 16) | (c4 << 24);
        unsigned m = max(max(c1, c2), max(c3, c4));
        unsigned y = (u + 0x10101010u) - m * 0x01010101u;   // tied bytes carry into bit4
        unsigned msk = (y >> 4) & 0x01010101u;              // 1 per tied byte
        unsigned code = (unsigned)__dp4a(msk, 0x08040201u, 0u);  // bit k <-> value k+1 tied
        if (m == 0u) code = 0u;
        unsigned den = m ? m : 1u;
        lut1[state] = (unsigned char)(den | (code << 4));
    }
    // ---- build LUT2: byte -> (out f32, den f32) ----
    if (threadIdx.x < 256) {
        unsigned t = threadIdx.x;
        unsigned code = t >> 4, den = t & 15u;
        unsigned n = __popc(code);
        unsigned s = (code & 1u) + 2u * ((code >> 1) & 1u)
                   + 3u * ((code >> 2) & 1u) + 4u * ((code >> 3) & 1u);
        float o = n ? __fdividef((float)s, (float)n) : 0.0f;
        lut2[t] = make_float2(o, (float)den);
    }
    __syncthreads();

    int wid = blockIdx.x * WPB + (threadIdx.x >> 5);
    if (wid >= NWARP) return;
    int lane = threadIdx.x & 31;
    int cg = lane & 3;        // channel group (4 floats)
    int b  = lane >> 2;       // batch
    int l0 = wid * U;
    int lend = min(l0 + U, LOUT);

    const float4 *xin = reinterpret_cast<const float4 *>(x) + (size_t)b * LL * 4 + cg;
    float4 *outp = reinterpret_cast<float4 *>(out) + (size_t)b * LOUT * 4 + cg;
    float4 *denp = outp + (size_t)BB * LOUT * 4;   // density tensor follows out

    // FULL iff every touched index is in range: max read l0+27+6, all 28 stored
    if (l0 + U + 5 < LL && lend == l0 + U)
        run_chunk<true>(xin, outp, denp, l0, lend, lut1, lut2);
    else
        run_chunk<false>(xin, outp, denp, l0, lend, lut1, lut2);
}

extern "C" void kernel_launch(void* const* d_in, const int* in_sizes, int n_in,
                              void* d_out, int out_size) {
    const float *x = (const float *)d_in[0];
    float *out = (float *)d_out;
    MaxOccurrencePool_kernel<<<NBLK, 512, SMEM_BYTES>>>(x, out);
}

// round 6
// speedup vs baseline: 1.1430x; 1.1430x over previous
#include <cuda_runtime.h>

// MaxOccurrencePool: sliding-window (K=9) mode-with-tie-average + max-count over
// integer values 0..4 (values 1..4 counted, bin0 only when window empty).
// x: [B=8, L=131072, C=16] f32. Outputs: out [B,L-1,C] f32 then density [B,L-1,C] f32.
//
// R5: back to ALU consume (R4 LUT was smem-bound). Fix the real R1-R3 limiter
//     (LDG latency, MLP=1, 6.5 warps/SMSP):
//       - prefetch queue depth 3 (rotation-free: 9-step unroll, 9 % 3 == 0)
//       - 10 CTAs/SM via __launch_bounds__(128,10) (48 regs)
//       - magic-add float->int (no F2I cvt), SIMD consume (vmax4/vcmpeq4/dp4a)

#define BB    8
#define LL    131072
#define LOUT  131071               // L - 1 output positions
#define U     27                   // positions per warp (3 ring periods)
#define NWARP ((LOUT + U - 1) / U) // 4855
#define NBLK  ((NWARP + 3) / 4)    // 1214 CTAs

#define MAGIC 8388608.0f           // 2^23: f + MAGIC -> low mantissa bits = (int)f

// one-hot byte for value iv in 0..4: byte (iv-1) = 1, or 0 for iv==0
__device__ __forceinline__ unsigned oh(unsigned iv) {
    return __funnelshift_lc(0x01000000u, 0u, iv << 3);
}
// float (integer-valued, 0..4) -> int without F2I
__device__ __forceinline__ unsigned fint(float f) {
    return __float_as_uint(f + MAGIC) & 7u;
}

// h = packed byte counts (c1..c4) -> out (tie-averaged argmax) + density
__device__ __forceinline__ void consume(unsigned h, float &outv, float &den) {
    unsigned t = __vmaxu4(h, h >> 16);
    t = __vmaxu4(t, t >> 8);
    unsigned m = t & 0xFFu;
    unsigned msk = __vcmpeq4(h, m * 0x01010101u) & 0x01010101u; // 1 per tied byte
    unsigned n = __dp4a(msk, 0x01010101u, 0u);                  // #ties (1..4)
    unsigned s = __dp4a(msk, 0x04030201u, 0u);                  // sum tied indices
    float o = __fdividef((float)s, (float)n);
    outv = (m == 0u) ? 0.0f : o;     // empty window -> bin0 -> 0
    den  = (float)max(m, 1u);        // empty window -> density 1
}

template <bool FULL>
__device__ __forceinline__ void step(int l, int ji, int lend,
                                     const float4 *__restrict__ xin,
                                     float4 *__restrict__ outp,
                                     float4 *__restrict__ denp,
                                     unsigned &h0, unsigned &h1,
                                     unsigned &h2, unsigned &h3,
                                     unsigned ring[9],
                                     float4 &q0, float4 &q1, float4 &q2) {
    unsigned i0 = fint(q0.x), i1 = fint(q0.y), i2 = fint(q0.z), i3 = fint(q0.w);

    // prefetch position l+8 (depth 3)
    float4 nq = make_float4(0.f, 0.f, 0.f, 0.f);
    int pn = l + 8;
    if (FULL) {
        nq = xin[pn * 4];
    } else if ((unsigned)pn < (unsigned)LL) {
        nq = xin[pn * 4];
    }

    unsigned old = ring[ji];
    ring[ji] = i0 | (i1 << 4) | (i2 << 8) | (i3 << 12);

    // outgoing one-hots from packed nibbles: shift amount = nib*8
    unsigned od0 = __funnelshift_lc(0x01000000u, 0u, (old << 3) & 0x78u);
    unsigned od1 = __funnelshift_lc(0x01000000u, 0u, (old >> 1) & 0x78u);
    unsigned od2 = __funnelshift_lc(0x01000000u, 0u, (old >> 5) & 0x78u);
    unsigned od3 = __funnelshift_lc(0x01000000u, 0u, (old >> 9) & 0x78u);

    h0 += oh(i0) - od0;
    h1 += oh(i1) - od1;
    h2 += oh(i2) - od2;
    h3 += oh(i3) - od3;

    float4 o, dn;
    consume(h0, o.x, dn.x);
    consume(h1, o.y, dn.y);
    consume(h2, o.z, dn.z);
    consume(h3, o.w, dn.w);

    if (FULL || l < lend) {
        __stcs(&outp[l * 4], o);
        __stcs(&denp[l * 4], dn);
    }
    q0 = q1; q1 = q2; q2 = nq;   // renamed away: 9-step unroll, 9 % 3 == 0
}

template <bool FULL>
__device__ __forceinline__ void run_chunk(const float4 *__restrict__ xin,
                                          float4 *__restrict__ outp,
                                          float4 *__restrict__ denp,
                                          int l0, int lend) {
    unsigned h0 = 0, h1 = 0, h2 = 0, h3 = 0;
    unsigned ring[9];                 // nibble-packed raw values of 4 channels

    // Prefill with positions p = l0-4 .. l0+4. OOB (padding) -> value 0.
    #pragma unroll
    for (int k = 0; k < 9; k++) {
        int p = l0 - 4 + k;
        float4 v = make_float4(0.f, 0.f, 0.f, 0.f);
        if ((unsigned)p < (unsigned)LL) v = xin[p * 4];
        unsigned i0 = fint(v.x), i1 = fint(v.y), i2 = fint(v.z), i3 = fint(v.w);
        ring[k] = i0 | (i1 << 4) | (i2 << 8) | (i3 << 12);
        h0 += oh(i0); h1 += oh(i1); h2 += oh(i2); h3 += oh(i3);
    }

    // prime 3-deep prefetch queue: positions l0+5, l0+6, l0+7
    float4 q0 = make_float4(0.f, 0.f, 0.f, 0.f);
    float4 q1 = q0, q2 = q0;
    {
        int p = l0 + 5;
        if (FULL || (unsigned)p < (unsigned)LL) q0 = xin[p * 4];
        if (FULL || (unsigned)(p + 1) < (unsigned)LL) q1 = xin[(p + 1) * 4];
        if (FULL || (unsigned)(p + 2) < (unsigned)LL) q2 = xin[(p + 2) * 4];
    }

    #pragma unroll 1
    for (int jo = 0; jo < 3; jo++) {
        #pragma unroll
        for (int ji = 0; ji < 9; ji++)
            step<FULL>(l0 + jo * 9 + ji, ji, lend, xin, outp, denp,
                       h0, h1, h2, h3, ring, q0, q1, q2);
    }
}

__global__ void __launch_bounds__(128, 10)
MaxOccurrencePool_kernel(const float *__restrict__ x, float *__restrict__ out) {
    int t = blockIdx.x * 128 + threadIdx.x;
    int wid = t >> 5;
    if (wid >= NWARP) return;
    int lane = t & 31;
    int cg = lane & 3;        // channel group (4 floats)
    int b  = lane >> 2;       // batch
    int l0 = wid * U;
    int lend = min(l0 + U, LOUT);

    const float4 *xin = reinterpret_cast<const float4 *>(x) + (size_t)b * LL * 4 + cg;
    float4 *outp = reinterpret_cast<float4 *>(out) + (size_t)b * LOUT * 4 + cg;
    float4 *denp = outp + (size_t)BB * LOUT * 4;   // density tensor follows out

    // FULL iff max prefetched pos l0+26+8 < LL and all U outputs stored
    if (l0 + U + 7 < LL && lend == l0 + U)
        run_chunk<true>(xin, outp, denp, l0, lend);
    else
        run_chunk<false>(xin, outp, denp, l0, lend);
}

extern "C" void kernel_launch(void* const* d_in, const int* in_sizes, int n_in,
                              void* d_out, int out_size) {
    const float *x = (const float *)d_in[0];
    float *out = (float *)d_out;
    MaxOccurrencePool_kernel<<<NBLK, 128>>>(x, out);
}

// round 8
// speedup vs baseline: 1.4159x; 1.2388x over previous
#include <cuda_runtime.h>

// MaxOccurrencePool: sliding-window (K=9) mode-with-tie-average + max-count over
// integer values 0..4 (values 1..4 counted, bin0 only when window empty).
// x: [B=8, L=131072, C=16] f32. Outputs: out [B,L-1,C] f32 then density [B,L-1,C] f32.
//
// R6: latency-hiding round. R2's proven step body (byte-extract consume; no
//     emulated byte-SIMD). Changes: U=12 (10923 warps -> occupancy set by regs,
//     10 CTAs/SM @48 regs, ~62% occ), depth-3 prefetch queue, fully unrolled
//     single-trip chunk (slots j%9 compile-time, queue shifts renamed away).

#define BB    8
#define LL    131072
#define LOUT  131071               // L - 1 output positions
#define U     12                   // positions per warp
#define NWARP ((LOUT + U - 1) / U) // 10923
#define NBLK  ((NWARP + 3) / 4)    // 2731 CTAs

// one-hot byte for value iv in 0..4: byte (iv-1) = 1, or 0 for iv==0
__device__ __forceinline__ unsigned oh(unsigned iv) {
    return __funnelshift_lc(0x01000000u, 0u, iv << 3);
}

// h = packed byte counts (c1..c4) -> out (tie-averaged argmax) + density  (R2 version)
__device__ __forceinline__ void consume(unsigned h, float &outv, float &den) {
    unsigned c1 = h & 0xFFu;
    unsigned c2 = (h >> 8) & 0xFFu;
    unsigned c3 = (h >> 16) & 0xFFu;
    unsigned c4 = h >> 24;
    unsigned m  = max(max(c1, c2), max(c3, c4));
    unsigned y   = (h + 0x10101010u) - m * 0x01010101u;  // tied bytes carry into bit4
    unsigned msk = y & 0x10101010u;                      // 0x10 per tied byte
    unsigned s16 = __dp4a(msk, 0x04030201u, 0u);         // 16 * sum(tied indices)
    unsigned n16 = __dp4a(msk, 0x01010101u, 0u);         // 16 * num ties
    float o = __fdividef((float)s16, (float)n16);
    outv = (m == 0u) ? 0.0f : o;                         // empty window -> bin0 -> 0
    den  = (float)max(m, 1u);                            // empty window -> density 1
}

template <bool FULL>
__device__ __forceinline__ void step(int l, int ji, int lend,
                                     const float4 *__restrict__ xin,
                                     float4 *__restrict__ outp,
                                     float4 *__restrict__ denp,
                                     unsigned &h0, unsigned &h1,
                                     unsigned &h2, unsigned &h3,
                                     unsigned ring[9],
                                     float4 &q0, float4 &q1, float4 &q2) {
    unsigned i0 = (unsigned)(int)q0.x, i1 = (unsigned)(int)q0.y;
    unsigned i2 = (unsigned)(int)q0.z, i3 = (unsigned)(int)q0.w;

    // prefetch position l+8 (queue depth 3)
    float4 nq = make_float4(0.f, 0.f, 0.f, 0.f);
    int pn = l + 8;
    if (FULL) {
        nq = xin[pn * 4];
    } else if ((unsigned)pn < (unsigned)LL) {
        nq = xin[pn * 4];
    }

    unsigned old = ring[ji];
    ring[ji] = i0 | (i1 << 4) | (i2 << 8) | (i3 << 12);

    // outgoing one-hots from packed nibbles: shift amount = nib*8
    unsigned od0 = __funnelshift_lc(0x01000000u, 0u, (old << 3) & 0x78u);
    unsigned od1 = __funnelshift_lc(0x01000000u, 0u, (old >> 1) & 0x78u);
    unsigned od2 = __funnelshift_lc(0x01000000u, 0u, (old >> 5) & 0x78u);
    unsigned od3 = __funnelshift_lc(0x01000000u, 0u, (old >> 9) & 0x78u);

    h0 += oh(i0) - od0;
    h1 += oh(i1) - od1;
    h2 += oh(i2) - od2;
    h3 += oh(i3) - od3;

    float4 o, dn;
    consume(h0, o.x, dn.x);
    consume(h1, o.y, dn.y);
    consume(h2, o.z, dn.z);
    consume(h3, o.w, dn.w);

    if (FULL || l < lend) {
        __stcs(&outp[l * 4], o);
        __stcs(&denp[l * 4], dn);
    }
    q0 = q1; q1 = q2; q2 = nq;   // fully unrolled -> pure renaming
}

template <bool FULL>
__device__ __forceinline__ void run_chunk(const float4 *__restrict__ xin,
                                          float4 *__restrict__ outp,
                                          float4 *__restrict__ denp,
                                          int l0, int lend) {
    unsigned h0 = 0, h1 = 0, h2 = 0, h3 = 0;
    unsigned ring[9];                 // nibble-packed raw values of 4 channels

    // Prefill with positions p = l0-4 .. l0+4 (slot k). OOB (padding) -> value 0.
    #pragma unroll
    for (int k = 0; k < 9; k++) {
        int p = l0 - 4 + k;
        float4 v = make_float4(0.f, 0.f, 0.f, 0.f);
        if ((unsigned)p < (unsigned)LL) v = xin[p * 4];
        unsigned i0 = (unsigned)(int)v.x, i1 = (unsigned)(int)v.y;
        unsigned i2 = (unsigned)(int)v.z, i3 = (unsigned)(int)v.w;
        ring[k] = i0 | (i1 << 4) | (i2 << 8) | (i3 << 12);
        h0 += oh(i0); h1 += oh(i1); h2 += oh(i2); h3 += oh(i3);
    }

    // prime 3-deep prefetch queue: positions l0+5, l0+6, l0+7
    float4 q0 = make_float4(0.f, 0.f, 0.f, 0.f);
    float4 q1 = q0, q2 = q0;
    {
        int p = l0 + 5;
        if (FULL || (unsigned)p < (unsigned)LL) q0 = xin[p * 4];
        if (FULL || (unsigned)(p + 1) < (unsigned)LL) q1 = xin[(p + 1) * 4];
        if (FULL || (unsigned)(p + 2) < (unsigned)LL) q2 = xin[(p + 2) * 4];
    }

    // 12 steps fully unrolled; ring slot = j % 9 (compile-time)
    #pragma unroll
    for (int j = 0; j < U; j++)
        step<FULL>(l0 + j, j % 9, lend, xin, outp, denp,
                   h0, h1, h2, h3, ring, q0, q1, q2);
}

__global__ void __launch_bounds__(128, 10)
MaxOccurrencePool_kernel(const float *__restrict__ x, float *__restrict__ out) {
    int t = blockIdx.x * 128 + threadIdx.x;
    int wid = t >> 5;
    if (wid >= NWARP) return;
    int lane = t & 31;
    int cg = lane & 3;        // channel group (4 floats)
    int b  = lane >> 2;       // batch
    int l0 = wid * U;
    int lend = min(l0 + U, LOUT);

    const float4 *xin = reinterpret_cast<const float4 *>(x) + (size_t)b * LL * 4 + cg;
    float4 *outp = reinterpret_cast<float4 *>(out) + (size_t)b * LOUT * 4 + cg;
    float4 *denp = outp + (size_t)BB * LOUT * 4;   // density tensor follows out

    // FULL iff max prefetched pos l0+U-1+8 < LL and all U outputs stored
    if (l0 + U + 7 < LL && lend == l0 + U)
        run_chunk<true>(xin, outp, denp, l0, lend);
    else
        run_chunk<false>(xin, outp, denp, l0, lend);
}

extern "C" void kernel_launch(void* const* d_in, const int* in_sizes, int n_in,
                              void* d_out, int out_size) {
    const float *x = (const float *)d_in[0];
    float *out = (float *)d_out;
    MaxOccurrencePool_kernel<<<NBLK, 128>>>(x, out);
}

// round 9
// speedup vs baseline: 1.4381x; 1.0157x over previous
#include <cuda_runtime.h>

// MaxOccurrencePool: sliding-window (K=9, span [l-3,l+5]) mode-with-tie-average +
// max-count over integer values 0..4 (1..4 counted; bin0 only when window empty).
// x: [B=8, L=131072, C=16] f32. Outputs: out [B,L-1,C] f32 then density [B,L-1,C] f32.
//
// R7: cp.async smem staging kills LDG long-scoreboard stalls (R1-R6 all latency
//     bound ~50% issue). CTA=256thr/8 warps, U=9 outputs/warp (one ring period),
//     tile = 82 positions x 8 batches staged via cp.async.cg (zfill OOB), padded
//     stride (82+1)*64B -> conflict-free LDS.128. 42.5KB static smem, 5 CTA/SM.

#define BB    8
#define LL    131072
#define LOUT  131071               // L - 1 output positions
#define U     9                    // outputs per warp (= ring period)
#define WPB   8                    // warps per CTA
#define TILE  (U * WPB)            // 72 outputs per CTA
#define NBLK  ((LOUT + TILE - 1) / TILE)   // 1821
#define S     (TILE + 10)          // staged positions per batch: [l0-4, l0+TILE+5]
#define BSTR  ((S + 1) * 64)       // per-batch smem stride (pad 64B: bank shift 16)
#define MAGIC 8388608.0f           // 2^23

// one-hot byte for value iv in 0..4: byte (iv-1) = 1, or 0 for iv==0
__device__ __forceinline__ unsigned oh(unsigned iv) {
    return __funnelshift_lc(0x01000000u, 0u, iv << 3);
}
__device__ __forceinline__ unsigned fint(float f) {
    return __float_as_uint(f + MAGIC) & 7u;   // exact for integer-valued 0..4
}

// h = packed byte counts (c1..c4) -> out (tie-averaged argmax) + density
__device__ __forceinline__ void consume(unsigned h, float &outv, float &den) {
    unsigned c1 = h & 0xFFu;
    unsigned c2 = (h >> 8) & 0xFFu;
    unsigned c3 = (h >> 16) & 0xFFu;
    unsigned c4 = h >> 24;
    unsigned m  = max(max(c1, c2), max(c3, c4));
    unsigned y   = (h + 0x10101010u) - m * 0x01010101u;  // tied bytes carry into bit4
    unsigned msk = y & 0x10101010u;                      // 0x10 per tied byte
    unsigned s16 = __dp4a(msk, 0x04030201u, 0u);         // 16 * sum(tied indices)
    unsigned n16 = __dp4a(msk, 0x01010101u, 0u);         // 16 * num ties
    float o = __fdividef((float)s16, (float)n16);
    outv = (m == 0u) ? 0.0f : o;                         // empty window -> bin0 -> 0
    den  = (float)max(m, 1u);                            // empty window -> density 1
}

__global__ void __launch_bounds__(256, 5)
MaxOccurrencePool_kernel(const float *__restrict__ x, float *__restrict__ out) {
    __shared__ __align__(16) char sm[BB * BSTR];

    const int tid = threadIdx.x;
    const int l0cta = blockIdx.x * TILE;

    // ---- stage tile: x[b][l0cta-4 .. l0cta+TILE+5][16ch] via cp.async (zfill OOB)
    {
        const int total = BB * S * 4;              // 16B chunks
        #pragma unroll
        for (int t = tid; t < total; t += 256) {
            int b  = t / (S * 4);
            int r  = t - b * (S * 4);
            int li = r >> 2;
            int cg = r & 3;
            int p  = l0cta - 4 + li;
            unsigned ok = ((unsigned)p < (unsigned)LL);
            unsigned sz = ok ? 16u : 0u;
            int pc = ok ? p : 0;
            const float *g = x + ((size_t)b * LL + pc) * 16 + cg * 4;
            unsigned sa = (unsigned)__cvta_generic_to_shared(sm + b * BSTR + li * 64 + cg * 16);
            asm volatile("cp.async.cg.shared.global [%0], [%1], 16, %2;"
                         :: "r"(sa), "l"(g), "r"(sz));
        }
        asm volatile("cp.async.commit_group;");
        asm volatile("cp.async.wait_group 0;");
    }
    __syncthreads();

    const int w    = tid >> 5;
    const int lane = tid & 31;
    const int cg   = lane & 3;        // channel group (4 floats)
    const int b    = lane >> 2;       // batch
    const int l0   = l0cta + w * U;   // this warp's first output

    // smem element idx i (position p = l0cta-4+i) lives at sp[i*4] (float4)
    const float4 *sp = reinterpret_cast<const float4 *>(sm + b * BSTR + cg * 16);
    const int base = w * U;           // idx of position l0-4

    unsigned h0 = 0, h1 = 0, h2 = 0, h3 = 0;
    unsigned ring[9];                 // nibble-packed raw values of 4 channels

    // Prefill slots k=0..8 with positions l0-4..l0+4 (idx base+k)
    #pragma unroll
    for (int k = 0; k < 9; k++) {
        float4 v = sp[(base + k) * 4];
        unsigned i0 = fint(v.x), i1 = fint(v.y), i2 = fint(v.z), i3 = fint(v.w);
        ring[k] = i0 | (i1 << 4) | (i2 << 8) | (i3 << 12);
        h0 += oh(i0); h1 += oh(i1); h2 += oh(i2); h3 += oh(i3);
    }

    float4 *outp = reinterpret_cast<float4 *>(out) + (size_t)b * LOUT * 4 + cg;
    float4 *denp = outp + (size_t)BB * LOUT * 4;   // density tensor follows out

    // 9 steps; step j: incoming position l0+5+j (idx base+9+j), evict slot j
    #pragma unroll
    for (int j = 0; j < U; j++) {
        int l = l0 + j;
        float4 v = sp[(base + 9 + j) * 4];
        unsigned i0 = fint(v.x), i1 = fint(v.y), i2 = fint(v.z), i3 = fint(v.w);

        unsigned old = ring[j];
        ring[j] = i0 | (i1 << 4) | (i2 << 8) | (i3 << 12);

        unsigned od0 = __funnelshift_lc(0x01000000u, 0u, (old << 3) & 0x78u);
        unsigned od1 = __funnelshift_lc(0x01000000u, 0u, (old >> 1) & 0x78u);
        unsigned od2 = __funnelshift_lc(0x01000000u, 0u, (old >> 5) & 0x78u);
        unsigned od3 = __funnelshift_lc(0x01000000u, 0u, (old >> 9) & 0x78u);

        h0 += oh(i0) - od0;
        h1 += oh(i1) - od1;
        h2 += oh(i2) - od2;
        h3 += oh(i3) - od3;

        float4 o, dn;
        consume(h0, o.x, dn.x);
        consume(h1, o.y, dn.y);
        consume(h2, o.z, dn.z);
        consume(h3, o.w, dn.w);

        if (l < LOUT) {
            __stcs(&outp[l * 4], o);
            __stcs(&denp[l * 4], dn);
        }
    }
}

extern "C" void kernel_launch(void* const* d_in, const int* in_sizes, int n_in,
                              void* d_out, int out_size) {
    const float *x = (const float *)d_in[0];
    float *out = (float *)d_out;
    MaxOccurrencePool_kernel<<<NBLK, 256>>>(x, out);
}

// round 10
// speedup vs baseline: 1.5370x; 1.0688x over previous
#include <cuda_runtime.h>

// MaxOccurrencePool: sliding-window (K=9, span [l-3,l+5]) mode-with-tie-average +
// max-count over integer values 0..4 (1..4 counted; bin0 only when window empty).
// x: [B=8, L=131072, C=16] f32. Outputs: out [B,L-1,C] f32 then density [B,L-1,C] f32.
//
// R8: issue-bound trim. consume() replaced by shifted-max trick + 160-entry
//     float2 smem LUT (one LDS.64 yields out+den; no I2F/MUFU/SEL):
//       z = max32(h, h<<8, h<<16, h<<24)  -> top byte = m, z>>20 = m*16
//       y = (h+0x10101010) - m*0x01010101 -> bit4 marks tied bytes
//       idx = dp4a((y>>4)&0x01010101, 0x08040201, z>>20) = m*16 + tiepattern
//     LUT built overlapping the cp.async wait. Everything else = R7.

#define BB    8
#define LL    131072
#define LOUT  131071               // L - 1 output positions
#define U     9                    // outputs per warp (= ring period)
#define WPB   8                    // warps per CTA
#define TILE  (U * WPB)            // 72 outputs per CTA
#define NBLK  ((LOUT + TILE - 1) / TILE)   // 1821
#define S     (TILE + 10)          // staged positions per batch: [l0-4, l0+TILE+5]
#define BSTR  ((S + 1) * 64)       // per-batch smem stride (pad 64B)
#define MAGIC 8388608.0f           // 2^23

// one-hot byte for value iv in 0..4: byte (iv-1) = 1, or 0 for iv==0
__device__ __forceinline__ unsigned oh(unsigned iv) {
    return __funnelshift_lc(0x01000000u, 0u, iv << 3);
}
__device__ __forceinline__ unsigned fint(float f) {
    return __float_as_uint(f + MAGIC) & 7u;   // exact for integer-valued 0..4
}

// h = packed byte counts -> (out, den) via smem LUT. Counts <= 9 (high nibbles 0).
__device__ __forceinline__ float2 consume(unsigned h, const float2 *__restrict__ lut) {
    unsigned z = max(h, h << 8);
    z = max(z, h << 16);
    z = max(z, h << 24);                    // top byte of z = m
    unsigned t = (h + 0x10101010u) - (z >> 24) * 0x01010101u;
    unsigned mskb = (t >> 4) & 0x01010101u; // 1 per tied byte
    unsigned idx  = __dp4a(mskb, 0x08040201u, z >> 20);  // m*16 + pattern
    return lut[idx];
}

__global__ void __launch_bounds__(256, 5)
MaxOccurrencePool_kernel(const float *__restrict__ x, float *__restrict__ out) {
    __shared__ __align__(16) char sm[BB * BSTR];
    __shared__ __align__(8) float2 lut[160];

    const int tid = threadIdx.x;
    const int l0cta = blockIdx.x * TILE;

    // ---- stage tile: x[b][l0cta-4 .. l0cta+TILE+5][16ch] via cp.async (zfill OOB)
    {
        const int total = BB * S * 4;              // 16B chunks
        #pragma unroll
        for (int t = tid; t < total; t += 256) {
            int b  = t / (S * 4);
            int r  = t - b * (S * 4);
            int li = r >> 2;
            int cg = r & 3;
            int p  = l0cta - 4 + li;
            unsigned ok = ((unsigned)p < (unsigned)LL);
            unsigned sz = ok ? 16u : 0u;
            int pc = ok ? p : 0;
            const float *g = x + ((size_t)b * LL + pc) * 16 + cg * 4;
            unsigned sa = (unsigned)__cvta_generic_to_shared(sm + b * BSTR + li * 64 + cg * 16);
            asm volatile("cp.async.cg.shared.global [%0], [%1], 16, %2;"
                         :: "r"(sa), "l"(g), "r"(sz));
        }
        asm volatile("cp.async.commit_group;");
    }

    // ---- build consume LUT while cp.async is in flight ----
    if (tid < 160) {
        unsigned m = tid >> 4, pat = tid & 15u;
        unsigned n = __popc(pat);
        unsigned s = (pat & 1u) + 2u * ((pat >> 1) & 1u)
                   + 3u * ((pat >> 2) & 1u) + 4u * ((pat >> 3) & 1u);
        float o = (m && n) ? __fdividef((float)s, (float)n) : 0.0f;
        lut[tid] = make_float2(o, (float)max(m, 1u));
    }

    asm volatile("cp.async.wait_group 0;");
    __syncthreads();

    const int w    = tid >> 5;
    const int lane = tid & 31;
    const int cg   = lane & 3;        // channel group (4 floats)
    const int b    = lane >> 2;       // batch
    const int l0   = l0cta + w * U;   // this warp's first output

    // smem element idx i (position p = l0cta-4+i) lives at sp[i*4] (float4)
    const float4 *sp = reinterpret_cast<const float4 *>(sm + b * BSTR + cg * 16);
    const int base = w * U;           // idx of position l0-4

    unsigned h0 = 0, h1 = 0, h2 = 0, h3 = 0;
    unsigned ring[9];                 // nibble-packed raw values of 4 channels

    // Prefill slots k=0..8 with positions l0-4..l0+4 (idx base+k)
    #pragma unroll
    for (int k = 0; k < 9; k++) {
        float4 v = sp[(base + k) * 4];
        unsigned i0 = fint(v.x), i1 = fint(v.y), i2 = fint(v.z), i3 = fint(v.w);
        ring[k] = i0 | (i1 << 4) | (i2 << 8) | (i3 << 12);
        h0 += oh(i0); h1 += oh(i1); h2 += oh(i2); h3 += oh(i3);
    }

    float4 *outp = reinterpret_cast<float4 *>(out) + (size_t)b * LOUT * 4 + cg;
    float4 *denp = outp + (size_t)BB * LOUT * 4;   // density tensor follows out

    // 9 steps; step j: incoming position l0+5+j (idx base+9+j), evict slot j
    #pragma unroll
    for (int j = 0; j < U; j++) {
        int l = l0 + j;
        float4 v = sp[(base + 9 + j) * 4];
        unsigned i0 = fint(v.x), i1 = fint(v.y), i2 = fint(v.z), i3 = fint(v.w);

        unsigned old = ring[j];
        ring[j] = i0 | (i1 << 4) | (i2 << 8) | (i3 << 12);

        unsigned od0 = __funnelshift_lc(0x01000000u, 0u, (old << 3) & 0x78u);
        unsigned od1 = __funnelshift_lc(0x01000000u, 0u, (old >> 1) & 0x78u);
        unsigned od2 = __funnelshift_lc(0x01000000u, 0u, (old >> 5) & 0x78u);
        unsigned od3 = __funnelshift_lc(0x01000000u, 0u, (old >> 9) & 0x78u);

        h0 += oh(i0) - od0;
        h1 += oh(i1) - od1;
        h2 += oh(i2) - od2;
        h3 += oh(i3) - od3;

        float2 r0 = consume(h0, lut);
        float2 r1 = consume(h1, lut);
        float2 r2 = consume(h2, lut);
        float2 r3 = consume(h3, lut);

        if (l < LOUT) {
            __stcs(&outp[l * 4], make_float4(r0.x, r1.x, r2.x, r3.x));
            __stcs(&denp[l * 4], make_float4(r0.y, r1.y, r2.y, r3.y));
        }
    }
}

extern "C" void kernel_launch(void* const* d_in, const int* in_sizes, int n_in,
                              void* d_out, int out_size) {
    const float *x = (const float *)d_in[0];
    float *out = (float *)d_out;
    MaxOccurrencePool_kernel<<<NBLK, 256>>>(x, out);
}